// round 3
// baseline (speedup 1.0000x reference)
#include <cuda_runtime.h>
#include <math.h>

#define BATCH 8
#define SEQ   2048
#define DIM   512

// Scratch (allocation-free rule: __device__ globals).
// g_q/g_k/g_v: 32 MB each; g_sc: 128 MB.
__device__ float g_q[BATCH * SEQ * DIM];
__device__ float g_k[BATCH * SEQ * DIM];
__device__ float g_v[BATCH * SEQ * DIM];
__device__ float g_sc[(size_t)BATCH * SEQ * SEQ];

// ---------------------------------------------------------------------------
// Tiled SGEMM: C = scale * (A @ op(B)) [+ bias]
//   A: [M,K] row-major. TRANSB=false: B [K,N]; TRANSB=true: B [N,K] (C=A·B^T).
//   128x128 tile, BK=8, 256 threads, 8x8 micro-tile per thread.
//   All dims must be multiples: M,N %128==0, K %8==0 (true for every call here).
//   blockIdx.z batches via element strides sA/sB/sC.
// ---------------------------------------------------------------------------
template <bool TRANSB, bool HAS_BIAS>
__global__ __launch_bounds__(256, 2)
void sgemm_k(const float* __restrict__ Ag, const float* __restrict__ Bg,
             float* __restrict__ Cg, const float* __restrict__ bias,
             int M, int N, int K, float scale,
             size_t sA, size_t sB, size_t sC)
{
    const int t  = threadIdx.x;
    const int ty = t >> 4;        // 0..15 -> row group
    const int tx = t & 15;        // 0..15 -> col group
    const int m0 = blockIdx.y * 128;
    const int n0 = blockIdx.x * 128;

    const float* A  = Ag + (size_t)blockIdx.z * sA;
    const float* Bm = Bg + (size_t)blockIdx.z * sB;
    float*       C  = Cg + (size_t)blockIdx.z * sC;

    __shared__ float As[8][128];
    __shared__ float Bs[8][132];   // +4 pad; row stride 528B stays 16B-aligned

    float acc[8][8];
#pragma unroll
    for (int i = 0; i < 8; i++)
#pragma unroll
        for (int j = 0; j < 8; j++) acc[i][j] = 0.0f;

    // A-tile load mapping: 128 rows x 8 k, one float4 per thread
    const int arow = t >> 1;          // 0..127
    const int akh  = (t & 1) * 4;     // 0 or 4 (k offset)

    for (int k0 = 0; k0 < K; k0 += 8) {
        // ---- load A tile (transposed into As[k][m]) ----
        {
            float4 av = *(const float4*)(A + (size_t)(m0 + arow) * K + k0 + akh);
            As[akh + 0][arow] = av.x;
            As[akh + 1][arow] = av.y;
            As[akh + 2][arow] = av.z;
            As[akh + 3][arow] = av.w;
        }
        // ---- load B tile into Bs[k][n] ----
        if (TRANSB) {
            // B is [N,K]; need Bs[k][n] = B[n0+n][k0+k]
            const int nn = t >> 1;          // 0..127
            const int kh = (t & 1) * 4;
            float4 bv = *(const float4*)(Bm + (size_t)(n0 + nn) * K + k0 + kh);
            Bs[kh + 0][nn] = bv.x;
            Bs[kh + 1][nn] = bv.y;
            Bs[kh + 2][nn] = bv.z;
            Bs[kh + 3][nn] = bv.w;
        } else {
            // B is [K,N]; contiguous float4 rows
            const int kb = t >> 5;          // 0..7
            const int n4 = (t & 31) * 4;    // 0..124
            float4 bv = *(const float4*)(Bm + (size_t)(k0 + kb) * N + n0 + n4);
            *(float4*)&Bs[kb][n4] = bv;
        }
        __syncthreads();

        // ---- 128x128x8 FMA ----
#pragma unroll
        for (int kk = 0; kk < 8; kk++) {
            float4 a0 = *(const float4*)&As[kk][ty * 8];
            float4 a1 = *(const float4*)&As[kk][ty * 8 + 4];
            float4 b0 = *(const float4*)&Bs[kk][tx * 8];
            float4 b1 = *(const float4*)&Bs[kk][tx * 8 + 4];
            float a[8] = {a0.x, a0.y, a0.z, a0.w, a1.x, a1.y, a1.z, a1.w};
            float b[8] = {b0.x, b0.y, b0.z, b0.w, b1.x, b1.y, b1.z, b1.w};
#pragma unroll
            for (int i = 0; i < 8; i++)
#pragma unroll
                for (int j = 0; j < 8; j++)
                    acc[i][j] = fmaf(a[i], b[j], acc[i][j]);
        }
        __syncthreads();
    }

    // ---- epilogue ----
    float bb[8];
#pragma unroll
    for (int j = 0; j < 8; j++)
        bb[j] = HAS_BIAS ? bias[n0 + tx * 8 + j] : 0.0f;

#pragma unroll
    for (int i = 0; i < 8; i++) {
        size_t off = (size_t)(m0 + ty * 8 + i) * N + n0 + tx * 8;
        float4 o0, o1;
        o0.x = acc[i][0] * scale + bb[0];
        o0.y = acc[i][1] * scale + bb[1];
        o0.z = acc[i][2] * scale + bb[2];
        o0.w = acc[i][3] * scale + bb[3];
        o1.x = acc[i][4] * scale + bb[4];
        o1.y = acc[i][5] * scale + bb[5];
        o1.z = acc[i][6] * scale + bb[6];
        o1.w = acc[i][7] * scale + bb[7];
        *(float4*)(C + off)     = o0;
        *(float4*)(C + off + 4) = o1;
    }
}

// ---------------------------------------------------------------------------
// Row softmax over SEQ=2048 elements, one block (256 thr) per row, in-place.
// ---------------------------------------------------------------------------
__global__ __launch_bounds__(256)
void softmax_k(float* __restrict__ sc)
{
    float* row = sc + (size_t)blockIdx.x * SEQ;
    const int t = threadIdx.x;

    float v[8];
    float m = -INFINITY;
#pragma unroll
    for (int i = 0; i < 8; i++) {
        v[i] = row[t + i * 256];
        m = fmaxf(m, v[i]);
    }
#pragma unroll
    for (int o = 16; o; o >>= 1) m = fmaxf(m, __shfl_xor_sync(0xffffffffu, m, o));

    __shared__ float redm[8];
    __shared__ float reds[8];
    if ((t & 31) == 0) redm[t >> 5] = m;
    __syncthreads();
#pragma unroll
    for (int i = 0; i < 8; i++) m = fmaxf(m, redm[i]);

    float s = 0.0f;
#pragma unroll
    for (int i = 0; i < 8; i++) {
        v[i] = __expf(v[i] - m);
        s += v[i];
    }
#pragma unroll
    for (int o = 16; o; o >>= 1) s += __shfl_xor_sync(0xffffffffu, s, o);
    if ((t & 31) == 0) reds[t >> 5] = s;
    __syncthreads();
    s = 0.0f;
#pragma unroll
    for (int i = 0; i < 8; i++) s += reds[i];

    const float inv = 1.0f / s;
#pragma unroll
    for (int i = 0; i < 8; i++) row[t + i * 256] = v[i] * inv;
}

// ---------------------------------------------------------------------------
// Launch: QKV GEMMs -> scores (NT, scaled) -> softmax -> PV (NN) -> d_out
// ---------------------------------------------------------------------------
extern "C" void kernel_launch(void* const* d_in, const int* in_sizes, int n_in,
                              void* d_out, int out_size)
{
    const float* x  = (const float*)d_in[0];
    const float* Wq = (const float*)d_in[1];
    const float* bq = (const float*)d_in[2];
    const float* Wk = (const float*)d_in[3];
    const float* bk = (const float*)d_in[4];
    const float* Wv = (const float*)d_in[5];
    const float* bv = (const float*)d_in[6];
    float* out = (float*)d_out;

    float *q, *k, *v, *sc;
    cudaGetSymbolAddress((void**)&q,  g_q);
    cudaGetSymbolAddress((void**)&k,  g_k);
    cudaGetSymbolAddress((void**)&v,  g_v);
    cudaGetSymbolAddress((void**)&sc, g_sc);

    const int MROWS = BATCH * SEQ;           // 16384
    const size_t sQKV = (size_t)SEQ * DIM;   // per-batch stride for q/k/v
    const size_t sSC  = (size_t)SEQ * SEQ;   // per-batch stride for scores
    const float inv_sqrt_d = 0.044194173824159216f;  // 1/sqrt(512)

    dim3 blk(256);

    // Projections: [16384,512] = x[16384,512] @ W[512,512] + b
    dim3 gproj(DIM / 128, MROWS / 128, 1);
    sgemm_k<false, true><<<gproj, blk>>>(x, Wq, q, bq, MROWS, DIM, DIM, 1.0f, 0, 0, 0);
    sgemm_k<false, true><<<gproj, blk>>>(x, Wk, k, bk, MROWS, DIM, DIM, 1.0f, 0, 0, 0);
    sgemm_k<false, true><<<gproj, blk>>>(x, Wv, v, bv, MROWS, DIM, DIM, 1.0f, 0, 0, 0);

    // Scores: per batch, [2048,2048] = Q @ K^T * (1/sqrt(D))
    dim3 gsc(SEQ / 128, SEQ / 128, BATCH);
    sgemm_k<true, false><<<gsc, blk>>>(q, k, sc, nullptr, SEQ, SEQ, DIM,
                                       inv_sqrt_d, sQKV, sQKV, sSC);

    // Softmax over last dim, in-place
    softmax_k<<<BATCH * SEQ, blk>>>(sc);

    // Output: per batch, [2048,512] = P @ V
    dim3 gpv(DIM / 128, SEQ / 128, BATCH);
    sgemm_k<false, false><<<gpv, blk>>>(sc, v, out, nullptr, SEQ, DIM, SEQ,
                                        1.0f, sSC, sQKV, sQKV);
}

// round 6
// speedup vs baseline: 2.1064x; 2.1064x over previous
#include <cuda_runtime.h>
#include <cuda_bf16.h>
#include <math.h>
#include <stdint.h>

#define BATCH 8
#define SEQ   2048
#define DIM   512

typedef __nv_bfloat16 bf16;

// ---------------- scratch (__device__ globals; no allocs allowed) ----------
__device__ bf16 g_xh[BATCH * SEQ * DIM];
__device__ bf16 g_xl[BATCH * SEQ * DIM];
__device__ bf16 g_wqh[DIM * DIM], g_wql[DIM * DIM];
__device__ bf16 g_wkh[DIM * DIM], g_wkl[DIM * DIM];
__device__ bf16 g_wvh[DIM * DIM], g_wvl[DIM * DIM];
__device__ bf16 g_qh[BATCH * SEQ * DIM], g_ql[BATCH * SEQ * DIM];
__device__ bf16 g_kh[BATCH * SEQ * DIM], g_kl[BATCH * SEQ * DIM];
__device__ bf16 g_vth[BATCH * SEQ * DIM], g_vtl[BATCH * SEQ * DIM];   // V^T [z][n][s]
__device__ bf16 g_sh[(size_t)BATCH * SEQ * SEQ];                      // scores / P hi
__device__ bf16 g_sl[(size_t)BATCH * SEQ * SEQ];                      // scores / P lo

// ---------------- PTX helpers (baseline sm_80-era only; no 'a' features) ----
__device__ __forceinline__ uint32_t smem_u32(const void* p) {
    uint32_t a;
    asm("{ .reg .u64 t; cvta.to.shared.u64 t, %1; cvt.u32.u64 %0, t; }" : "=r"(a) : "l"(p));
    return a;
}
__device__ __forceinline__ void cpa16(uint32_t s, const void* g) {
    asm volatile("cp.async.cg.shared.global [%0], [%1], 16;" :: "r"(s), "l"(g));
}
__device__ __forceinline__ void cpa_commit() { asm volatile("cp.async.commit_group;" ::: "memory"); }
__device__ __forceinline__ void cpa_wait1()  { asm volatile("cp.async.wait_group 1;" ::: "memory"); }
__device__ __forceinline__ void cpa_wait0()  { asm volatile("cp.async.wait_group 0;" ::: "memory"); }

__device__ __forceinline__ void ldsm4(uint32_t* r, uint32_t addr) {
    asm volatile("ldmatrix.sync.aligned.m8n8.x4.shared.b16 {%0,%1,%2,%3}, [%4];"
                 : "=r"(r[0]), "=r"(r[1]), "=r"(r[2]), "=r"(r[3]) : "r"(addr));
}
__device__ __forceinline__ void mma16816(float* c, const uint32_t* a, const uint32_t* b) {
    asm volatile("mma.sync.aligned.m16n8k16.row.col.f32.bf16.bf16.f32 "
                 "{%0,%1,%2,%3}, {%4,%5,%6,%7}, {%8,%9}, {%0,%1,%2,%3};"
                 : "+f"(c[0]), "+f"(c[1]), "+f"(c[2]), "+f"(c[3])
                 : "r"(a[0]), "r"(a[1]), "r"(a[2]), "r"(a[3]), "r"(b[0]), "r"(b[1]));
}

// ---------------- GEMM geometry ---------------------------------------------
// Block tile 128x128, BK=32. 8 warps: 4(m) x 2(n); warp tile 32x64.
// Smem rows padded to 40 bf16 (80B) -> conflict-free ldmatrix.
#define BK        32
#define LDA       40
#define TILE_B    (128 * LDA * 2)          // 10240 B per tile
#define STAGE_B   (4 * TILE_B)             // Ah, Al, Bh, Bl = 40960 B
#define GEMM_SMEM (2 * STAGE_B)            // 81920 B

// One chunk of A or B (128 rows x 32 k, bf16) into padded swizzle-free smem.
__device__ __forceinline__ void fill_tile(uint32_t st, const bf16* __restrict__ g,
                                          int ldg, int tid) {
#pragma unroll
    for (int i = 0; i < 2; i++) {
        int lin = i * 256 + tid;       // 0..511
        int r = lin >> 2, s = lin & 3;
        cpa16(st + (uint32_t)(r * LDA + s * 8) * 2, g + (size_t)r * ldg + s * 8);
    }
}

// ---------------- GEMM: D = scale*(A @ B^T) [+bias], bf16x3 on HMMA ---------
// A:[M,K] hi/lo K-major.  B:[N,K] hi/lo K-major.
// OMODE 0: fp32 out. 1: bf16 hi/lo out (+bias). 2: transposed bf16 hi/lo out (+bias).
template <int OMODE, bool HASB>
__global__ __launch_bounds__(256, 1)
void gemm_mma(const bf16* __restrict__ Ah, const bf16* __restrict__ Al, size_t sAz,
              const bf16* __restrict__ Bh, const bf16* __restrict__ Bl, size_t sBz,
              const float* __restrict__ bias,
              float* __restrict__ Of, bf16* __restrict__ Oh, bf16* __restrict__ Ol,
              size_t sCz, int ldC, int K, float scale)
{
    extern __shared__ char smem[];
    const uint32_t sb = smem_u32(smem);
    const int tid  = threadIdx.x;
    const int lane = tid & 31;
    const int wid  = tid >> 5;
    const int m_warp = (wid & 3) * 32;       // 4 warps along m
    const int n_warp = (wid >> 2) * 64;      // 2 warps along n
    const int m0 = blockIdx.y * 128, n0 = blockIdx.x * 128;
    const size_t z = blockIdx.z;

    const bf16* Abh = Ah + z * sAz + (size_t)m0 * K;
    const bf16* Abl = Al + z * sAz + (size_t)m0 * K;
    const bf16* Bbh = Bh + z * sBz + (size_t)n0 * K;
    const bf16* Bbl = Bl + z * sBz + (size_t)n0 * K;

    float acc[2][8][4];
#pragma unroll
    for (int f = 0; f < 2; f++)
#pragma unroll
        for (int j = 0; j < 8; j++)
#pragma unroll
            for (int e = 0; e < 4; e++) acc[f][j][e] = 0.0f;

    const int nch = K / BK;

    // ldmatrix source offsets (within a tile), canonical x4 thread->row maps
    const uint32_t a_off = (uint32_t)(((lane & 15) * LDA + (lane >> 4) * 8) * 2);
    const uint32_t b_off = (uint32_t)((((lane >> 4) * 8 + (lane & 7)) * LDA
                                       + ((lane >> 3) & 1) * 8) * 2);

    // prologue: stage 0 <- chunk 0
    {
        uint32_t st = sb;
        fill_tile(st,              Abh, K, tid);
        fill_tile(st + TILE_B,     Abl, K, tid);
        fill_tile(st + 2 * TILE_B, Bbh, K, tid);
        fill_tile(st + 3 * TILE_B, Bbl, K, tid);
        cpa_commit();
    }

    for (int c = 0; c < nch; c++) {
        if (c + 1 < nch) {
            uint32_t st = sb + ((c + 1) & 1) * STAGE_B;
            fill_tile(st,              Abh + (c + 1) * BK, K, tid);
            fill_tile(st + TILE_B,     Abl + (c + 1) * BK, K, tid);
            fill_tile(st + 2 * TILE_B, Bbh + (c + 1) * BK, K, tid);
            fill_tile(st + 3 * TILE_B, Bbl + (c + 1) * BK, K, tid);
            cpa_commit();
            cpa_wait1();
        } else {
            cpa_wait0();
        }
        __syncthreads();

        const uint32_t st   = sb + (c & 1) * STAGE_B;
        const uint32_t sAh_ = st;
        const uint32_t sAl_ = st + TILE_B;
        const uint32_t sBh_ = st + 2 * TILE_B;
        const uint32_t sBl_ = st + 3 * TILE_B;

#pragma unroll
        for (int s = 0; s < 2; s++) {            // two k16 steps per chunk
            const uint32_t kb = (uint32_t)(s * 16 * 2);
            uint32_t ah[2][4], al[2][4];
#pragma unroll
            for (int f = 0; f < 2; f++) {
                const uint32_t ro = (uint32_t)((m_warp + f * 16) * LDA * 2);
                ldsm4(ah[f], sAh_ + ro + a_off + kb);
                ldsm4(al[f], sAl_ + ro + a_off + kb);
            }
            uint32_t bh[8][2], bl[8][2];
#pragma unroll
            for (int p = 0; p < 4; p++) {        // each x4 covers two n8 frags
                const uint32_t ro = (uint32_t)((n_warp + p * 16) * LDA * 2);
                uint32_t t[4];
                ldsm4(t, sBh_ + ro + b_off + kb);
                bh[2*p][0] = t[0]; bh[2*p][1] = t[1];
                bh[2*p+1][0] = t[2]; bh[2*p+1][1] = t[3];
                ldsm4(t, sBl_ + ro + b_off + kb);
                bl[2*p][0] = t[0]; bl[2*p][1] = t[1];
                bl[2*p+1][0] = t[2]; bl[2*p+1][1] = t[3];
            }
#pragma unroll
            for (int f = 0; f < 2; f++)
#pragma unroll
                for (int j = 0; j < 8; j++) {
                    mma16816(acc[f][j], ah[f], bh[j]);   // hi*hi
                    mma16816(acc[f][j], ah[f], bl[j]);   // hi*lo
                    mma16816(acc[f][j], al[f], bh[j]);   // lo*hi
                }
        }
        __syncthreads();
    }

    // ---- epilogue ----
    const int rq = lane >> 2;            // row within 8
    const int cq = (lane & 3) * 2;       // col pair
#pragma unroll
    for (int f = 0; f < 2; f++) {
        const int rbase = m0 + m_warp + f * 16 + rq;
#pragma unroll
        for (int j = 0; j < 8; j++) {
            const int cg = n0 + n_warp + j * 8 + cq;
#pragma unroll
            for (int h = 0; h < 2; h++) {            // h=0: row, h=1: row+8
                const int r = rbase + h * 8;
                float v0 = acc[f][j][2 * h + 0] * scale;
                float v1 = acc[f][j][2 * h + 1] * scale;
                if (OMODE == 0) {
                    float2 o; o.x = v0; o.y = v1;
                    *(float2*)(Of + z * sCz + (size_t)r * ldC + cg) = o;
                } else if (OMODE == 1) {
                    if (HASB) { v0 += bias[cg]; v1 += bias[cg + 1]; }
                    bf16 h0 = __float2bfloat16(v0), h1 = __float2bfloat16(v1);
                    bf16 l0 = __float2bfloat16(v0 - __bfloat162float(h0));
                    bf16 l1 = __float2bfloat16(v1 - __bfloat162float(h1));
                    __nv_bfloat162 hp; hp.x = h0; hp.y = h1;
                    __nv_bfloat162 lp; lp.x = l0; lp.y = l1;
                    const size_t o = z * sCz + (size_t)r * ldC + cg;
                    *(__nv_bfloat162*)(Oh + o) = hp;
                    *(__nv_bfloat162*)(Ol + o) = lp;
                } else {                              // transposed (V^T)
                    if (HASB) { v0 += bias[cg]; v1 += bias[cg + 1]; }
                    bf16 h0 = __float2bfloat16(v0), h1 = __float2bfloat16(v1);
                    bf16 l0 = __float2bfloat16(v0 - __bfloat162float(h0));
                    bf16 l1 = __float2bfloat16(v1 - __bfloat162float(h1));
                    const size_t o0 = z * sCz + (size_t)cg * ldC + r;
                    const size_t o1 = o0 + ldC;
                    Oh[o0] = h0; Ol[o0] = l0;
                    Oh[o1] = h1; Ol[o1] = l1;
                }
            }
        }
    }
}

// ---------------- split kernels ---------------------------------------------
__global__ __launch_bounds__(256)
void split_k(const float* __restrict__ s, bf16* __restrict__ h, bf16* __restrict__ l, int n)
{
    int i = blockIdx.x * blockDim.x + threadIdx.x;
    if (i < n) {
        float v = s[i];
        bf16 hi = __float2bfloat16(v);
        h[i] = hi;
        l[i] = __float2bfloat16(v - __bfloat162float(hi));
    }
}

// W [K=512, N=512] row-major -> W^T hi/lo [N=512, K=512] K-major
__global__ __launch_bounds__(256)
void splitT_k(const float* __restrict__ w, bf16* __restrict__ h, bf16* __restrict__ l)
{
    int i = blockIdx.x * blockDim.x + threadIdx.x;   // 0..262143
    int n_ = i >> 9, k_ = i & 511;
    float v = w[(size_t)k_ * DIM + n_];
    bf16 hi = __float2bfloat16(v);
    h[i] = hi;
    l[i] = __float2bfloat16(v - __bfloat162float(hi));
}

// ---------------- softmax on hi/lo rows, in place ---------------------------
__global__ __launch_bounds__(256)
void softmax_k(bf16* __restrict__ sh, bf16* __restrict__ sl)
{
    const size_t ro = (size_t)blockIdx.x * SEQ;
    const int t = threadIdx.x;

    float v[8];
    float m = -INFINITY;
#pragma unroll
    for (int i = 0; i < 8; i++) {
        const size_t idx = ro + t + i * 256;
        v[i] = __bfloat162float(sh[idx]) + __bfloat162float(sl[idx]);
        m = fmaxf(m, v[i]);
    }
#pragma unroll
    for (int o = 16; o; o >>= 1) m = fmaxf(m, __shfl_xor_sync(0xffffffffu, m, o));

    __shared__ float redm[8], reds[8];
    if ((t & 31) == 0) redm[t >> 5] = m;
    __syncthreads();
#pragma unroll
    for (int i = 0; i < 8; i++) m = fmaxf(m, redm[i]);

    float s = 0.0f;
#pragma unroll
    for (int i = 0; i < 8; i++) { v[i] = __expf(v[i] - m); s += v[i]; }
#pragma unroll
    for (int o = 16; o; o >>= 1) s += __shfl_xor_sync(0xffffffffu, s, o);
    if ((t & 31) == 0) reds[t >> 5] = s;
    __syncthreads();
    s = 0.0f;
#pragma unroll
    for (int i = 0; i < 8; i++) s += reds[i];

    const float inv = 1.0f / s;
#pragma unroll
    for (int i = 0; i < 8; i++) {
        const size_t idx = ro + t + i * 256;
        float p = v[i] * inv;
        bf16 hi = __float2bfloat16(p);
        sh[idx] = hi;
        sl[idx] = __float2bfloat16(p - __bfloat162float(hi));
    }
}

// ---------------- launch -----------------------------------------------------
extern "C" void kernel_launch(void* const* d_in, const int* in_sizes, int n_in,
                              void* d_out, int out_size)
{
    const float* x  = (const float*)d_in[0];
    const float* Wq = (const float*)d_in[1];
    const float* bq = (const float*)d_in[2];
    const float* Wk = (const float*)d_in[3];
    const float* bk = (const float*)d_in[4];
    const float* Wv = (const float*)d_in[5];
    const float* bv = (const float*)d_in[6];
    float* out = (float*)d_out;

    bf16 *xh, *xl, *wqh, *wql, *wkh, *wkl, *wvh, *wvl;
    bf16 *qh, *ql, *kh, *kl, *vth, *vtl, *sh_, *sl_;
    cudaGetSymbolAddress((void**)&xh,  g_xh);  cudaGetSymbolAddress((void**)&xl,  g_xl);
    cudaGetSymbolAddress((void**)&wqh, g_wqh); cudaGetSymbolAddress((void**)&wql, g_wql);
    cudaGetSymbolAddress((void**)&wkh, g_wkh); cudaGetSymbolAddress((void**)&wkl, g_wkl);
    cudaGetSymbolAddress((void**)&wvh, g_wvh); cudaGetSymbolAddress((void**)&wvl, g_wvl);
    cudaGetSymbolAddress((void**)&qh,  g_qh);  cudaGetSymbolAddress((void**)&ql,  g_ql);
    cudaGetSymbolAddress((void**)&kh,  g_kh);  cudaGetSymbolAddress((void**)&kl,  g_kl);
    cudaGetSymbolAddress((void**)&vth, g_vth); cudaGetSymbolAddress((void**)&vtl, g_vtl);
    cudaGetSymbolAddress((void**)&sh_, g_sh);  cudaGetSymbolAddress((void**)&sl_, g_sl);

    cudaFuncSetAttribute(gemm_mma<0, false>, cudaFuncAttributeMaxDynamicSharedMemorySize, GEMM_SMEM);
    cudaFuncSetAttribute(gemm_mma<1, false>, cudaFuncAttributeMaxDynamicSharedMemorySize, GEMM_SMEM);
    cudaFuncSetAttribute(gemm_mma<1, true>,  cudaFuncAttributeMaxDynamicSharedMemorySize, GEMM_SMEM);
    cudaFuncSetAttribute(gemm_mma<2, true>,  cudaFuncAttributeMaxDynamicSharedMemorySize, GEMM_SMEM);

    const int NX = BATCH * SEQ * DIM;                    // 8M
    const size_t SD  = (size_t)SEQ * DIM;
    const size_t SS  = (size_t)SEQ * SEQ;
    const float inv_sqrt_d = 0.044194173824159216f;      // 1/sqrt(512)

    split_k<<<(NX + 255) / 256, 256>>>(x, xh, xl, NX);
    splitT_k<<<(DIM * DIM) / 256, 256>>>(Wq, wqh, wql);
    splitT_k<<<(DIM * DIM) / 256, 256>>>(Wk, wkh, wkl);
    splitT_k<<<(DIM * DIM) / 256, 256>>>(Wv, wvh, wvl);

    // Projections: per batch M=2048, N=512, K=512
    dim3 gproj(DIM / 128, SEQ / 128, BATCH);
    gemm_mma<1, true><<<gproj, 256, GEMM_SMEM>>>(xh, xl, SD, wqh, wql, 0, bq,
                                                 nullptr, qh, ql, SD, DIM, DIM, 1.0f);
    gemm_mma<1, true><<<gproj, 256, GEMM_SMEM>>>(xh, xl, SD, wkh, wkl, 0, bk,
                                                 nullptr, kh, kl, SD, DIM, DIM, 1.0f);
    // V projection written transposed: vt[z][n][s]
    gemm_mma<2, true><<<gproj, 256, GEMM_SMEM>>>(xh, xl, SD, wvh, wvl, 0, bv,
                                                 nullptr, vth, vtl, SD, SEQ, DIM, 1.0f);

    // Scores: per batch [2048,2048] = Q @ K^T * scale -> hi/lo
    dim3 gsc(SEQ / 128, SEQ / 128, BATCH);
    gemm_mma<1, false><<<gsc, 256, GEMM_SMEM>>>(qh, ql, SD, kh, kl, SD, nullptr,
                                                nullptr, sh_, sl_, SS, SEQ, DIM, inv_sqrt_d);

    softmax_k<<<BATCH * SEQ, 256>>>(sh_, sl_);

    // Out: per batch [2048,512] = P @ (V^T)^T, fp32 to d_out
    dim3 gpv(DIM / 128, SEQ / 128, BATCH);
    gemm_mma<0, false><<<gpv, 256, GEMM_SMEM>>>(sh_, sl_, SS, vth, vtl, SD, nullptr,
                                                out, nullptr, nullptr, SD, DIM, SEQ, 1.0f);
}

// round 7
// speedup vs baseline: 5.6655x; 2.6896x over previous
#include <cuda_runtime.h>
#include <cuda_fp16.h>
#include <math.h>
#include <stdint.h>

#define BATCH 8
#define SEQ   2048
#define DIM   512

typedef __half fp16;

// ---------------- scratch (__device__ globals; no allocs allowed) ----------
__device__ fp16 g_x [BATCH * SEQ * DIM];
__device__ fp16 g_wq[DIM * DIM], g_wk[DIM * DIM], g_wv[DIM * DIM];   // W^T [n][k]
__device__ fp16 g_q [BATCH * SEQ * DIM];
__device__ fp16 g_k [BATCH * SEQ * DIM];
__device__ fp16 g_vt[BATCH * SEQ * DIM];                             // V^T [z][n][s]
__device__ fp16 g_s [(size_t)BATCH * SEQ * SEQ];                     // scores / P

// ---------------- PTX helpers (baseline sm_80-era only) ---------------------
__device__ __forceinline__ uint32_t smem_u32(const void* p) {
    uint32_t a;
    asm("{ .reg .u64 t; cvta.to.shared.u64 t, %1; cvt.u32.u64 %0, t; }" : "=r"(a) : "l"(p));
    return a;
}
__device__ __forceinline__ void cpa16(uint32_t s, const void* g) {
    asm volatile("cp.async.cg.shared.global [%0], [%1], 16;" :: "r"(s), "l"(g));
}
__device__ __forceinline__ void cpa_commit() { asm volatile("cp.async.commit_group;" ::: "memory"); }
__device__ __forceinline__ void cpa_wait1()  { asm volatile("cp.async.wait_group 1;" ::: "memory"); }
__device__ __forceinline__ void cpa_wait0()  { asm volatile("cp.async.wait_group 0;" ::: "memory"); }

__device__ __forceinline__ void ldsm4(uint32_t* r, uint32_t addr) {
    asm volatile("ldmatrix.sync.aligned.m8n8.x4.shared.b16 {%0,%1,%2,%3}, [%4];"
                 : "=r"(r[0]), "=r"(r[1]), "=r"(r[2]), "=r"(r[3]) : "r"(addr));
}
__device__ __forceinline__ void mma16816(float* c, const uint32_t* a, const uint32_t* b) {
    asm volatile("mma.sync.aligned.m16n8k16.row.col.f32.f16.f16.f32 "
                 "{%0,%1,%2,%3}, {%4,%5,%6,%7}, {%8,%9}, {%0,%1,%2,%3};"
                 : "+f"(c[0]), "+f"(c[1]), "+f"(c[2]), "+f"(c[3])
                 : "r"(a[0]), "r"(a[1]), "r"(a[2]), "r"(a[3]), "r"(b[0]), "r"(b[1]));
}

// ---------------- GEMM geometry ---------------------------------------------
// Block tile 128x128, BK=32. 8 warps: 4(m) x 2(n); warp tile 32x64.
// Smem rows padded to 40 fp16 (80B) -> conflict-free ldmatrix.
#define BK        32
#define LDA       40
#define TILE_B    (128 * LDA * 2)          // 10240 B per tile
#define STAGE_B   (2 * TILE_B)             // A, B = 20480 B
#define GEMM_SMEM (2 * STAGE_B)            // 40960 B (2 stages)

// One chunk (128 rows x 32 k, fp16) into padded smem.
__device__ __forceinline__ void fill_tile(uint32_t st, const fp16* __restrict__ g,
                                          int ldg, int tid) {
#pragma unroll
    for (int i = 0; i < 2; i++) {
        int lin = i * 256 + tid;       // 0..511
        int r = lin >> 2, s = lin & 3;
        cpa16(st + (uint32_t)(r * LDA + s * 8) * 2, g + (size_t)r * ldg + s * 8);
    }
}

// ---------------- GEMM: D = scale*(A @ B^T) [+bias], single fp16 HMMA -------
// A:[M,K] K-major.  B:[N,K] K-major.
// OMODE 0: fp32 out. 1: fp16 out (+bias). 2: transposed fp16 out (+bias).
template <int OMODE, bool HASB>
__global__ __launch_bounds__(256, 2)
void gemm_mma(const fp16* __restrict__ A, size_t sAz,
              const fp16* __restrict__ B, size_t sBz,
              const float* __restrict__ bias,
              float* __restrict__ Of, fp16* __restrict__ Oh,
              size_t sCz, int ldC, int K, float scale)
{
    extern __shared__ char smem[];
    const uint32_t sb = smem_u32(smem);
    const int tid  = threadIdx.x;
    const int lane = tid & 31;
    const int wid  = tid >> 5;
    const int m_warp = (wid & 3) * 32;       // 4 warps along m
    const int n_warp = (wid >> 2) * 64;      // 2 warps along n
    const int m0 = blockIdx.y * 128, n0 = blockIdx.x * 128;
    const size_t z = blockIdx.z;

    const fp16* Ab = A + z * sAz + (size_t)m0 * K;
    const fp16* Bb = B + z * sBz + (size_t)n0 * K;

    float acc[2][8][4];
#pragma unroll
    for (int f = 0; f < 2; f++)
#pragma unroll
        for (int j = 0; j < 8; j++)
#pragma unroll
            for (int e = 0; e < 4; e++) acc[f][j][e] = 0.0f;

    const int nch = K / BK;

    // ldmatrix source offsets (within a tile), canonical x4 thread->row maps
    const uint32_t a_off = (uint32_t)(((lane & 15) * LDA + (lane >> 4) * 8) * 2);
    const uint32_t b_off = (uint32_t)((((lane >> 4) * 8 + (lane & 7)) * LDA
                                       + ((lane >> 3) & 1) * 8) * 2);

    // prologue: stage 0 <- chunk 0
    {
        fill_tile(sb,          Ab, K, tid);
        fill_tile(sb + TILE_B, Bb, K, tid);
        cpa_commit();
    }

    for (int c = 0; c < nch; c++) {
        if (c + 1 < nch) {
            uint32_t st = sb + ((c + 1) & 1) * STAGE_B;
            fill_tile(st,          Ab + (c + 1) * BK, K, tid);
            fill_tile(st + TILE_B, Bb + (c + 1) * BK, K, tid);
            cpa_commit();
            cpa_wait1();
        } else {
            cpa_wait0();
        }
        __syncthreads();

        const uint32_t st  = sb + (c & 1) * STAGE_B;
        const uint32_t sA_ = st;
        const uint32_t sB_ = st + TILE_B;

#pragma unroll
        for (int s = 0; s < 2; s++) {            // two k16 steps per chunk
            const uint32_t kb = (uint32_t)(s * 16 * 2);
            uint32_t af[2][4];
#pragma unroll
            for (int f = 0; f < 2; f++) {
                const uint32_t ro = (uint32_t)((m_warp + f * 16) * LDA * 2);
                ldsm4(af[f], sA_ + ro + a_off + kb);
            }
            uint32_t bfr[8][2];
#pragma unroll
            for (int p = 0; p < 4; p++) {        // each x4 covers two n8 frags
                const uint32_t ro = (uint32_t)((n_warp + p * 16) * LDA * 2);
                uint32_t t[4];
                ldsm4(t, sB_ + ro + b_off + kb);
                bfr[2*p][0]   = t[0]; bfr[2*p][1]   = t[1];
                bfr[2*p+1][0] = t[2]; bfr[2*p+1][1] = t[3];
            }
#pragma unroll
            for (int f = 0; f < 2; f++)
#pragma unroll
                for (int j = 0; j < 8; j++)
                    mma16816(acc[f][j], af[f], bfr[j]);
        }
        __syncthreads();
    }

    // ---- epilogue ----
    const int rq = lane >> 2;            // row within 8
    const int cq = (lane & 3) * 2;       // col pair
#pragma unroll
    for (int f = 0; f < 2; f++) {
        const int rbase = m0 + m_warp + f * 16 + rq;
#pragma unroll
        for (int j = 0; j < 8; j++) {
            const int cg = n0 + n_warp + j * 8 + cq;
#pragma unroll
            for (int h = 0; h < 2; h++) {            // h=0: row, h=1: row+8
                const int r = rbase + h * 8;
                float v0 = acc[f][j][2 * h + 0] * scale;
                float v1 = acc[f][j][2 * h + 1] * scale;
                if (OMODE == 0) {
                    float2 o; o.x = v0; o.y = v1;
                    *(float2*)(Of + z * sCz + (size_t)r * ldC + cg) = o;
                } else if (OMODE == 1) {
                    if (HASB) { v0 += bias[cg]; v1 += bias[cg + 1]; }
                    __half2 hp; hp.x = __float2half(v0); hp.y = __float2half(v1);
                    *(__half2*)(Oh + z * sCz + (size_t)r * ldC + cg) = hp;
                } else {                              // transposed (V^T)
                    if (HASB) { v0 += bias[cg]; v1 += bias[cg + 1]; }
                    const size_t o0 = z * sCz + (size_t)cg * ldC + r;
                    Oh[o0]       = __float2half(v0);
                    Oh[o0 + ldC] = __float2half(v1);
                }
            }
        }
    }
}

// ---------------- split kernels ---------------------------------------------
__global__ __launch_bounds__(256)
void tofp16_k(const float* __restrict__ s, fp16* __restrict__ h, int n)
{
    int i = blockIdx.x * blockDim.x + threadIdx.x;
    if (i < n) h[i] = __float2half(s[i]);
}

// W [K=512, N=512] row-major -> W^T fp16 [N=512, K=512] K-major
__global__ __launch_bounds__(256)
void tofp16T_k(const float* __restrict__ w, fp16* __restrict__ h)
{
    int i = blockIdx.x * blockDim.x + threadIdx.x;   // 0..262143
    int n_ = i >> 9, k_ = i & 511;
    h[i] = __float2half(w[(size_t)k_ * DIM + n_]);
}

// ---------------- softmax on fp16 rows, in place ----------------------------
__global__ __launch_bounds__(256)
void softmax_k(fp16* __restrict__ sc)
{
    const size_t ro = (size_t)blockIdx.x * SEQ;
    const int t = threadIdx.x;

    float v[8];
    float m = -INFINITY;
#pragma unroll
    for (int i = 0; i < 8; i++) {
        v[i] = __half2float(sc[ro + t + i * 256]);
        m = fmaxf(m, v[i]);
    }
#pragma unroll
    for (int o = 16; o; o >>= 1) m = fmaxf(m, __shfl_xor_sync(0xffffffffu, m, o));

    __shared__ float redm[8], reds[8];
    if ((t & 31) == 0) redm[t >> 5] = m;
    __syncthreads();
#pragma unroll
    for (int i = 0; i < 8; i++) m = fmaxf(m, redm[i]);

    float s = 0.0f;
#pragma unroll
    for (int i = 0; i < 8; i++) { v[i] = __expf(v[i] - m); s += v[i]; }
#pragma unroll
    for (int o = 16; o; o >>= 1) s += __shfl_xor_sync(0xffffffffu, s, o);
    if ((t & 31) == 0) reds[t >> 5] = s;
    __syncthreads();
    s = 0.0f;
#pragma unroll
    for (int i = 0; i < 8; i++) s += reds[i];

    const float inv = 1.0f / s;
#pragma unroll
    for (int i = 0; i < 8; i++)
        sc[ro + t + i * 256] = __float2half(v[i] * inv);
}

// ---------------- launch -----------------------------------------------------
extern "C" void kernel_launch(void* const* d_in, const int* in_sizes, int n_in,
                              void* d_out, int out_size)
{
    const float* x  = (const float*)d_in[0];
    const float* Wq = (const float*)d_in[1];
    const float* bq = (const float*)d_in[2];
    const float* Wk = (const float*)d_in[3];
    const float* bk = (const float*)d_in[4];
    const float* Wv = (const float*)d_in[5];
    const float* bv = (const float*)d_in[6];
    float* out = (float*)d_out;

    fp16 *xh, *wq, *wk, *wv, *q, *k, *vt, *sc;
    cudaGetSymbolAddress((void**)&xh, g_x);
    cudaGetSymbolAddress((void**)&wq, g_wq);
    cudaGetSymbolAddress((void**)&wk, g_wk);
    cudaGetSymbolAddress((void**)&wv, g_wv);
    cudaGetSymbolAddress((void**)&q,  g_q);
    cudaGetSymbolAddress((void**)&k,  g_k);
    cudaGetSymbolAddress((void**)&vt, g_vt);
    cudaGetSymbolAddress((void**)&sc, g_s);

    cudaFuncSetAttribute(gemm_mma<0, false>, cudaFuncAttributeMaxDynamicSharedMemorySize, GEMM_SMEM);
    cudaFuncSetAttribute(gemm_mma<1, false>, cudaFuncAttributeMaxDynamicSharedMemorySize, GEMM_SMEM);
    cudaFuncSetAttribute(gemm_mma<1, true>,  cudaFuncAttributeMaxDynamicSharedMemorySize, GEMM_SMEM);
    cudaFuncSetAttribute(gemm_mma<2, true>,  cudaFuncAttributeMaxDynamicSharedMemorySize, GEMM_SMEM);

    const int NX = BATCH * SEQ * DIM;                    // 8M
    const size_t SD  = (size_t)SEQ * DIM;
    const size_t SS  = (size_t)SEQ * SEQ;
    const float inv_sqrt_d = 0.044194173824159216f;      // 1/sqrt(512)

    tofp16_k<<<(NX + 255) / 256, 256>>>(x, xh, NX);
    tofp16T_k<<<(DIM * DIM) / 256, 256>>>(Wq, wq);
    tofp16T_k<<<(DIM * DIM) / 256, 256>>>(Wk, wk);
    tofp16T_k<<<(DIM * DIM) / 256, 256>>>(Wv, wv);

    // Projections: per batch M=2048, N=512, K=512
    dim3 gproj(DIM / 128, SEQ / 128, BATCH);
    gemm_mma<1, true><<<gproj, 256, GEMM_SMEM>>>(xh, SD, wq, 0, bq,
                                                 nullptr, q, SD, DIM, DIM, 1.0f);
    gemm_mma<1, true><<<gproj, 256, GEMM_SMEM>>>(xh, SD, wk, 0, bk,
                                                 nullptr, k, SD, DIM, DIM, 1.0f);
    // V projection written transposed: vt[z][n][s]
    gemm_mma<2, true><<<gproj, 256, GEMM_SMEM>>>(xh, SD, wv, 0, bv,
                                                 nullptr, vt, SD, SEQ, DIM, 1.0f);

    // Scores: per batch [2048,2048] = Q @ K^T * scale -> fp16
    dim3 gsc(SEQ / 128, SEQ / 128, BATCH);
    gemm_mma<1, false><<<gsc, 256, GEMM_SMEM>>>(q, SD, k, SD, nullptr,
                                                nullptr, sc, SS, SEQ, DIM, inv_sqrt_d);

    softmax_k<<<BATCH * SEQ, 256>>>(sc);

    // Out: per batch [2048,512] = P @ (V^T)^T, fp32 to d_out
    dim3 gpv(DIM / 128, SEQ / 128, BATCH);
    gemm_mma<0, false><<<gpv, 256, GEMM_SMEM>>>(sc, SS, vt, SD, nullptr,
                                                out, nullptr, SD, DIM, SEQ, 1.0f);
}

// round 8
// speedup vs baseline: 6.9235x; 1.2221x over previous
#include <cuda_runtime.h>
#include <cuda_fp16.h>
#include <math.h>
#include <stdint.h>

#define BATCH 8
#define SEQ   2048
#define DIM   512

typedef __half fp16;

// ---------------- scratch (__device__ globals; no allocs allowed) ----------
__device__ fp16 g_x [BATCH * SEQ * DIM];
__device__ fp16 g_wq[DIM * DIM], g_wk[DIM * DIM], g_wv[DIM * DIM];   // W^T [n][k]
__device__ fp16 g_q [BATCH * SEQ * DIM];
__device__ fp16 g_k [BATCH * SEQ * DIM];
__device__ fp16 g_vt[BATCH * SEQ * DIM];                             // V^T [z][n][s]
__device__ fp16 g_s [(size_t)BATCH * SEQ * SEQ];                     // scores / P

// ---------------- PTX helpers (baseline sm_80-era only) ---------------------
__device__ __forceinline__ uint32_t smem_u32(const void* p) {
    uint32_t a;
    asm("{ .reg .u64 t; cvta.to.shared.u64 t, %1; cvt.u32.u64 %0, t; }" : "=r"(a) : "l"(p));
    return a;
}
__device__ __forceinline__ void cpa16(uint32_t s, const void* g) {
    asm volatile("cp.async.cg.shared.global [%0], [%1], 16;" :: "r"(s), "l"(g));
}
__device__ __forceinline__ void cpa_commit() { asm volatile("cp.async.commit_group;" ::: "memory"); }
__device__ __forceinline__ void cpa_wait2()  { asm volatile("cp.async.wait_group 2;" ::: "memory"); }
__device__ __forceinline__ void cpa_wait1()  { asm volatile("cp.async.wait_group 1;" ::: "memory"); }
__device__ __forceinline__ void cpa_wait0()  { asm volatile("cp.async.wait_group 0;" ::: "memory"); }

__device__ __forceinline__ void ldsm4(uint32_t* r, uint32_t addr) {
    asm volatile("ldmatrix.sync.aligned.m8n8.x4.shared.b16 {%0,%1,%2,%3}, [%4];"
                 : "=r"(r[0]), "=r"(r[1]), "=r"(r[2]), "=r"(r[3]) : "r"(addr));
}
__device__ __forceinline__ void mma16816(float* c, const uint32_t* a, const uint32_t* b) {
    asm volatile("mma.sync.aligned.m16n8k16.row.col.f32.f16.f16.f32 "
                 "{%0,%1,%2,%3}, {%4,%5,%6,%7}, {%8,%9}, {%0,%1,%2,%3};"
                 : "+f"(c[0]), "+f"(c[1]), "+f"(c[2]), "+f"(c[3])
                 : "r"(a[0]), "r"(a[1]), "r"(a[2]), "r"(a[3]), "r"(b[0]), "r"(b[1]));
}

// ---------------- GEMM geometry ---------------------------------------------
// Block tile 128x128, BK=32, 3 stages. 4 warps: 2(m) x 2(n); warp tile 64x64.
// Smem rows padded to 40 fp16 (80B) -> conflict-free ldmatrix.
#define BK        32
#define LDA       40
#define TILE_B    (128 * LDA * 2)          // 10240 B per tile
#define STAGE_B   (2 * TILE_B)             // A, B = 20480 B
#define NSTAGE    3
#define GEMM_SMEM (NSTAGE * STAGE_B)       // 61440 B

// One chunk (128 rows x 32 k, fp16) into padded smem. 128 threads.
__device__ __forceinline__ void fill_tile(uint32_t st, const fp16* __restrict__ g,
                                          int ldg, int tid) {
#pragma unroll
    for (int i = 0; i < 4; i++) {
        int lin = i * 128 + tid;       // 0..511
        int r = lin >> 2, s = lin & 3;
        cpa16(st + (uint32_t)(r * LDA + s * 8) * 2, g + (size_t)r * ldg + s * 8);
    }
}

// ---------------- GEMM: D = scale*(A @ B^T) [+bias], single fp16 HMMA -------
// A:[M,K] K-major.  B:[N,K] K-major.
// OMODE 0: fp32 out. 1: fp16 out (+bias). 2: transposed fp16 out (+bias).
template <int OMODE, bool HASB>
__global__ __launch_bounds__(128, 2)
void gemm_mma(const fp16* __restrict__ A, size_t sAz,
              const fp16* __restrict__ B, size_t sBz,
              const float* __restrict__ bias,
              float* __restrict__ Of, fp16* __restrict__ Oh,
              size_t sCz, int ldC, int K, float scale)
{
    extern __shared__ char smem[];
    const uint32_t sb = smem_u32(smem);
    const int tid  = threadIdx.x;
    const int lane = tid & 31;
    const int wid  = tid >> 5;
    const int m_warp = (wid & 1) * 64;       // 2 warps along m
    const int n_warp = (wid >> 1) * 64;      // 2 warps along n
    const int m0 = blockIdx.y * 128, n0 = blockIdx.x * 128;
    const size_t z = blockIdx.z;

    const fp16* Ab = A + z * sAz + (size_t)m0 * K;
    const fp16* Bb = B + z * sBz + (size_t)n0 * K;

    float acc[4][8][4];
#pragma unroll
    for (int f = 0; f < 4; f++)
#pragma unroll
        for (int j = 0; j < 8; j++)
#pragma unroll
            for (int e = 0; e < 4; e++) acc[f][j][e] = 0.0f;

    const int nch = K / BK;   // >= 16 for all calls here

    // ldmatrix source offsets (within a tile), canonical x4 thread->row maps
    const uint32_t a_off = (uint32_t)(((lane & 15) * LDA + (lane >> 4) * 8) * 2);
    const uint32_t b_off = (uint32_t)((((lane >> 4) * 8 + (lane & 7)) * LDA
                                       + ((lane >> 3) & 1) * 8) * 2);

    // prologue: stages 0,1 <- chunks 0,1
    fill_tile(sb,          Ab, K, tid);
    fill_tile(sb + TILE_B, Bb, K, tid);
    cpa_commit();
    fill_tile(sb + STAGE_B,          Ab + BK, K, tid);
    fill_tile(sb + STAGE_B + TILE_B, Bb + BK, K, tid);
    cpa_commit();

    for (int c = 0; c < nch; c++) {
        // pending groups before this iter: chunks c, c+1 (when they exist)
        if (c + 2 < nch) {
            uint32_t st = sb + ((c + 2) % 3) * STAGE_B;
            fill_tile(st,          Ab + (c + 2) * BK, K, tid);
            fill_tile(st + TILE_B, Bb + (c + 2) * BK, K, tid);
            cpa_commit();
            cpa_wait2();          // pending {c,c+1,c+2} -> chunk c resident
        } else if (c + 1 < nch) {
            cpa_wait1();          // pending {c,c+1} -> chunk c resident
        } else {
            cpa_wait0();
        }
        __syncthreads();

        const uint32_t st  = sb + (c % 3) * STAGE_B;
        const uint32_t sA_ = st;
        const uint32_t sB_ = st + TILE_B;

#pragma unroll
        for (int s = 0; s < 2; s++) {            // two k16 steps per chunk
            const uint32_t kb = (uint32_t)(s * 16 * 2);
            uint32_t af[4][4];
#pragma unroll
            for (int f = 0; f < 4; f++) {
                const uint32_t ro = (uint32_t)((m_warp + f * 16) * LDA * 2);
                ldsm4(af[f], sA_ + ro + a_off + kb);
            }
            uint32_t bfr[8][2];
#pragma unroll
            for (int p = 0; p < 4; p++) {        // each x4 covers two n8 frags
                const uint32_t ro = (uint32_t)((n_warp + p * 16) * LDA * 2);
                uint32_t t[4];
                ldsm4(t, sB_ + ro + b_off + kb);
                bfr[2*p][0]   = t[0]; bfr[2*p][1]   = t[1];
                bfr[2*p+1][0] = t[2]; bfr[2*p+1][1] = t[3];
            }
#pragma unroll
            for (int f = 0; f < 4; f++)
#pragma unroll
                for (int j = 0; j < 8; j++)
                    mma16816(acc[f][j], af[f], bfr[j]);
        }
        __syncthreads();
    }

    // ---- epilogue ----
    const int rq = lane >> 2;            // row within 8
    const int cq = (lane & 3) * 2;       // col pair
#pragma unroll
    for (int f = 0; f < 4; f++) {
        const int rbase = m0 + m_warp + f * 16 + rq;
#pragma unroll
        for (int j = 0; j < 8; j++) {
            const int cg = n0 + n_warp + j * 8 + cq;
#pragma unroll
            for (int h = 0; h < 2; h++) {            // h=0: row, h=1: row+8
                const int r = rbase + h * 8;
                float v0 = acc[f][j][2 * h + 0] * scale;
                float v1 = acc[f][j][2 * h + 1] * scale;
                if (OMODE == 0) {
                    float2 o; o.x = v0; o.y = v1;
                    *(float2*)(Of + z * sCz + (size_t)r * ldC + cg) = o;
                } else if (OMODE == 1) {
                    if (HASB) { v0 += bias[cg]; v1 += bias[cg + 1]; }
                    __half2 hp; hp.x = __float2half(v0); hp.y = __float2half(v1);
                    *(__half2*)(Oh + z * sCz + (size_t)r * ldC + cg) = hp;
                } else {                              // transposed (V^T)
                    if (HASB) { v0 += bias[cg]; v1 += bias[cg + 1]; }
                    const size_t o0 = z * sCz + (size_t)cg * ldC + r;
                    Oh[o0]       = __float2half(v0);
                    Oh[o0 + ldC] = __float2half(v1);
                }
            }
        }
    }
}

// ---------------- convert kernels --------------------------------------------
// x fp32 -> fp16, vectorized (n multiple of 4)
__global__ __launch_bounds__(256)
void tofp16_k(const float* __restrict__ s, fp16* __restrict__ h, int n4)
{
    int i = blockIdx.x * blockDim.x + threadIdx.x;
    if (i < n4) {
        float4 v = ((const float4*)s)[i];
        __half2 a; a.x = __float2half(v.x); a.y = __float2half(v.y);
        __half2 b; b.x = __float2half(v.z); b.y = __float2half(v.w);
        ((__half2*)h)[2 * i]     = a;
        ((__half2*)h)[2 * i + 1] = b;
    }
}

// W [K=512,N=512] row-major fp32 -> W^T fp16 [N][K], coalesced via smem tile.
// grid (16,16,3), block (32,8). z selects (Wq,Wk,Wv).
__global__ __launch_bounds__(256)
void wtransT_k(const float* __restrict__ w0, const float* __restrict__ w1,
               const float* __restrict__ w2,
               fp16* __restrict__ o0, fp16* __restrict__ o1, fp16* __restrict__ o2)
{
    const float* w = (blockIdx.z == 0) ? w0 : (blockIdx.z == 1) ? w1 : w2;
    fp16*       o  = (blockIdx.z == 0) ? o0 : (blockIdx.z == 1) ? o1 : o2;
    __shared__ float s[32][33];
    const int tx = threadIdx.x, ty = threadIdx.y;
    const int k0 = blockIdx.x * 32, n0 = blockIdx.y * 32;
#pragma unroll
    for (int i = 0; i < 4; i++)
        s[ty + i * 8][tx] = w[(size_t)(k0 + ty + i * 8) * DIM + n0 + tx];
    __syncthreads();
#pragma unroll
    for (int i = 0; i < 4; i++)
        o[(size_t)(n0 + ty + i * 8) * DIM + k0 + tx] = __float2half(s[tx][ty + i * 8]);
}

// ---------------- softmax on fp16 rows, in place (half2 I/O) ----------------
__global__ __launch_bounds__(256)
void softmax_k(fp16* __restrict__ sc)
{
    __half2* row2 = (__half2*)(sc + (size_t)blockIdx.x * SEQ);   // 1024 half2
    const int t = threadIdx.x;

    float v[8];
    float m = -INFINITY;
#pragma unroll
    for (int i = 0; i < 4; i++) {
        float2 p = __half22float2(row2[t + i * 256]);
        v[2 * i] = p.x; v[2 * i + 1] = p.y;
        m = fmaxf(m, fmaxf(p.x, p.y));
    }
#pragma unroll
    for (int o = 16; o; o >>= 1) m = fmaxf(m, __shfl_xor_sync(0xffffffffu, m, o));

    __shared__ float redm[8], reds[8];
    if ((t & 31) == 0) redm[t >> 5] = m;
    __syncthreads();
#pragma unroll
    for (int i = 0; i < 8; i++) m = fmaxf(m, redm[i]);

    float s = 0.0f;
#pragma unroll
    for (int i = 0; i < 8; i++) { v[i] = __expf(v[i] - m); s += v[i]; }
#pragma unroll
    for (int o = 16; o; o >>= 1) s += __shfl_xor_sync(0xffffffffu, s, o);
    if ((t & 31) == 0) reds[t >> 5] = s;
    __syncthreads();
    s = 0.0f;
#pragma unroll
    for (int i = 0; i < 8; i++) s += reds[i];

    const float inv = 1.0f / s;
#pragma unroll
    for (int i = 0; i < 4; i++) {
        __half2 o; o.x = __float2half(v[2 * i] * inv); o.y = __float2half(v[2 * i + 1] * inv);
        row2[t + i * 256] = o;
    }
}

// ---------------- launch -----------------------------------------------------
extern "C" void kernel_launch(void* const* d_in, const int* in_sizes, int n_in,
                              void* d_out, int out_size)
{
    const float* x  = (const float*)d_in[0];
    const float* Wq = (const float*)d_in[1];
    const float* bq = (const float*)d_in[2];
    const float* Wk = (const float*)d_in[3];
    const float* bk = (const float*)d_in[4];
    const float* Wv = (const float*)d_in[5];
    const float* bv = (const float*)d_in[6];
    float* out = (float*)d_out;

    fp16 *xh, *wq, *wk, *wv, *q, *k, *vt, *sc;
    cudaGetSymbolAddress((void**)&xh, g_x);
    cudaGetSymbolAddress((void**)&wq, g_wq);
    cudaGetSymbolAddress((void**)&wk, g_wk);
    cudaGetSymbolAddress((void**)&wv, g_wv);
    cudaGetSymbolAddress((void**)&q,  g_q);
    cudaGetSymbolAddress((void**)&k,  g_k);
    cudaGetSymbolAddress((void**)&vt, g_vt);
    cudaGetSymbolAddress((void**)&sc, g_s);

    cudaFuncSetAttribute(gemm_mma<0, false>, cudaFuncAttributeMaxDynamicSharedMemorySize, GEMM_SMEM);
    cudaFuncSetAttribute(gemm_mma<1, false>, cudaFuncAttributeMaxDynamicSharedMemorySize, GEMM_SMEM);
    cudaFuncSetAttribute(gemm_mma<1, true>,  cudaFuncAttributeMaxDynamicSharedMemorySize, GEMM_SMEM);
    cudaFuncSetAttribute(gemm_mma<2, true>,  cudaFuncAttributeMaxDynamicSharedMemorySize, GEMM_SMEM);

    const int NX = BATCH * SEQ * DIM;                    // 8M
    const size_t SD  = (size_t)SEQ * DIM;
    const size_t SS  = (size_t)SEQ * SEQ;
    const float inv_sqrt_d = 0.044194173824159216f;      // 1/sqrt(512)

    tofp16_k<<<(NX / 4 + 255) / 256, 256>>>(x, xh, NX / 4);
    wtransT_k<<<dim3(16, 16, 3), dim3(32, 8)>>>(Wq, Wk, Wv, wq, wk, wv);

    // Projections: per batch M=2048, N=512, K=512
    dim3 gproj(DIM / 128, SEQ / 128, BATCH);
    gemm_mma<1, true><<<gproj, 128, GEMM_SMEM>>>(xh, SD, wq, 0, bq,
                                                 nullptr, q, SD, DIM, DIM, 1.0f);
    gemm_mma<1, true><<<gproj, 128, GEMM_SMEM>>>(xh, SD, wk, 0, bk,
                                                 nullptr, k, SD, DIM, DIM, 1.0f);
    // V projection written transposed: vt[z][n][s]
    gemm_mma<2, true><<<gproj, 128, GEMM_SMEM>>>(xh, SD, wv, 0, bv,
                                                 nullptr, vt, SD, SEQ, DIM, 1.0f);

    // Scores: per batch [2048,2048] = Q @ K^T * scale -> fp16
    dim3 gsc(SEQ / 128, SEQ / 128, BATCH);
    gemm_mma<1, false><<<gsc, 128, GEMM_SMEM>>>(q, SD, k, SD, nullptr,
                                                nullptr, sc, SS, SEQ, DIM, inv_sqrt_d);

    softmax_k<<<BATCH * SEQ, 256>>>(sc);

    // Out: per batch [2048,512] = P @ (V^T)^T, fp32 to d_out
    dim3 gpv(DIM / 128, SEQ / 128, BATCH);
    gemm_mma<0, false><<<gpv, 128, GEMM_SMEM>>>(sc, SS, vt, SD, nullptr,
                                                out, nullptr, SD, DIM, SEQ, 1.0f);
}